// round 6
// baseline (speedup 1.0000x reference)
#include <cuda_runtime.h>
#include <cuda_fp16.h>
#include <cuda_bf16.h>

#define N_NODES_MAX 100000
#define E_MAX       1600000
#define F           128
#define SCAN_CHUNK  1024
#define SCAN_GMAX   128      // ceil(100000/1024) = 98 <= 128

// Scratch (allocation-free contract: __device__ globals)
__device__ __half g_feat_h[(long)N_NODES_MAX * F]; // 25.6 MB fp16 features
__device__ int   g_deg[N_NODES_MAX];
__device__ int   g_row_start[N_NODES_MAX + 1];
__device__ int   g_cursor[N_NODES_MAX];
__device__ int   g_csr_src[E_MAX];                 // 6.4 MB
__device__ int   g_block_sums[SCAN_GMAX];
__device__ int   g_block_offsets[SCAN_GMAX];

// ---------------------------------------------------------------------------
// 0. convert feat fp32 -> fp16 (one float4 -> 2x half2 per thread-iter)
// ---------------------------------------------------------------------------
__global__ void convert_kernel(const float* __restrict__ feat, long total) {
    long i = (long)blockIdx.x * blockDim.x + threadIdx.x;   // float4 index
    long n4 = total / 4;
    for (; i < n4; i += (long)gridDim.x * blockDim.x) {
        float4 v = reinterpret_cast<const float4*>(feat)[i];
        __half2 h0 = __floats2half2_rn(v.x, v.y);
        __half2 h1 = __floats2half2_rn(v.z, v.w);
        uint2 packed;
        packed.x = *reinterpret_cast<unsigned*>(&h0);
        packed.y = *reinterpret_cast<unsigned*>(&h1);
        reinterpret_cast<uint2*>(g_feat_h)[i] = packed;
    }
}

// ---------------------------------------------------------------------------
// 1. histogram of dst
// ---------------------------------------------------------------------------
__global__ void hist_kernel(const int* __restrict__ dst, int n_edges) {
    int e = blockIdx.x * blockDim.x + threadIdx.x;
    if (e < n_edges) atomicAdd(&g_deg[dst[e]], 1);
}

// ---------------------------------------------------------------------------
// 2a. per-chunk sums
// ---------------------------------------------------------------------------
__global__ void __launch_bounds__(SCAN_CHUNK) scan1_kernel(int n_nodes) {
    __shared__ int s[SCAN_CHUNK];
    int t = threadIdx.x;
    int idx = blockIdx.x * SCAN_CHUNK + t;
    s[t] = (idx < n_nodes) ? g_deg[idx] : 0;
    __syncthreads();
    for (int off = SCAN_CHUNK / 2; off > 0; off >>= 1) {
        if (t < off) s[t] += s[t + off];
        __syncthreads();
    }
    if (t == 0) g_block_sums[blockIdx.x] = s[0];
}

// 2b. scan of chunk sums (single block)
__global__ void __launch_bounds__(SCAN_GMAX) scan2_kernel(int n_blocks, int n_nodes) {
    __shared__ int s[SCAN_GMAX];
    int t = threadIdx.x;
    int v = (t < n_blocks) ? g_block_sums[t] : 0;
    s[t] = v;
    __syncthreads();
    for (int off = 1; off < SCAN_GMAX; off <<= 1) {
        int add = (t >= off) ? s[t - off] : 0;
        __syncthreads();
        s[t] += add;
        __syncthreads();
    }
    if (t < n_blocks) g_block_offsets[t] = s[t] - v;   // exclusive
    if (t == SCAN_GMAX - 1) g_row_start[n_nodes] = s[SCAN_GMAX - 1];
}

// 2c. per-chunk exclusive scan + block offset -> row_start
__global__ void __launch_bounds__(SCAN_CHUNK) scan3_kernel(int n_nodes) {
    __shared__ int s[SCAN_CHUNK];
    int t = threadIdx.x;
    int idx = blockIdx.x * SCAN_CHUNK + t;
    int own = (idx < n_nodes) ? g_deg[idx] : 0;
    s[t] = own;
    __syncthreads();
    for (int off = 1; off < SCAN_CHUNK; off <<= 1) {
        int add = (t >= off) ? s[t - off] : 0;
        __syncthreads();
        s[t] += add;
        __syncthreads();
    }
    if (idx < n_nodes)
        g_row_start[idx] = g_block_offsets[blockIdx.x] + s[t] - own;
}

// ---------------------------------------------------------------------------
// 3. fill CSR: slot = row_start[dst] + cursor[dst]++
// ---------------------------------------------------------------------------
__global__ void fill_kernel(const int* __restrict__ src,
                            const int* __restrict__ dst, int n_edges) {
    int e = blockIdx.x * blockDim.x + threadIdx.x;
    if (e >= n_edges) return;
    int d = dst[e];
    int pos = atomicAdd(&g_cursor[d], 1);
    g_csr_src[g_row_start[d] + pos] = src[e];
}

// ---------------------------------------------------------------------------
// 4. fused gather + GEMM + norm + bias.
// Block: 256 threads handles 64 nodes.
//   Phase 1: warp w gathers nodes [rb+w*8, rb+w*8+8) from fp16 feat rows
//            (8B/lane per edge, fp32 accumulate) straight into smem tile.
//   Phase 2: register-tiled GEMM (8x4 micro-tile/thread) from smem,
//            epilogue applies rsqrt(max(deg,1)) and bias.
// ---------------------------------------------------------------------------
#define GM 64
__global__ void __launch_bounds__(256) fused_gather_gemm_kernel(
        const float* __restrict__ W,
        const float* __restrict__ bias,
        float* __restrict__ out,
        int n_nodes) {
    __shared__ float sA[GM * F];   // 32 KB

    int t = threadIdx.x;
    int lane = t & 31;
    int w = t >> 5;
    int rb = blockIdx.x * GM;

    const uint2* fh = reinterpret_cast<const uint2*>(g_feat_h);  // 32 uint2 per row
    float4* sA4 = reinterpret_cast<float4*>(sA);

    // ---- Phase 1: gather 8 nodes per warp ----
#pragma unroll
    for (int i = 0; i < 8; i++) {
        int node = rb + w * 8 + i;
        float4 acc = make_float4(0.f, 0.f, 0.f, 0.f);
        if (node < n_nodes) {
            int beg = g_row_start[node];
            int end = g_row_start[node + 1];
            for (int e = beg; e < end; e += 32) {
                int s_reg = (e + lane < end) ? g_csr_src[e + lane] : 0;
                int cnt = min(32, end - e);
#pragma unroll 8
                for (int j = 0; j < cnt; j++) {
                    int s = __shfl_sync(0xffffffffu, s_reg, j);
                    uint2 raw = __ldg(fh + (long)s * 32 + lane);
                    __half2 h0 = *reinterpret_cast<__half2*>(&raw.x);
                    __half2 h1 = *reinterpret_cast<__half2*>(&raw.y);
                    float2 f0 = __half22float2(h0);
                    float2 f1 = __half22float2(h1);
                    acc.x += f0.x; acc.y += f0.y;
                    acc.z += f1.x; acc.w += f1.y;
                }
            }
        }
        sA4[(w * 8 + i) * 32 + lane] = acc;   // cols lane*4..lane*4+3
    }
    __syncthreads();

    // ---- Phase 2: GEMM ----
    int cg = lane * 4;      // col base (0..124)
    int rg = w * 8;         // row base within tile (0..56)

    float acc[8][4];
#pragma unroll
    for (int i = 0; i < 8; i++)
#pragma unroll
        for (int j = 0; j < 4; j++) acc[i][j] = 0.f;

#pragma unroll 8
    for (int k = 0; k < F; k++) {
        float4 wv = __ldg(reinterpret_cast<const float4*>(W + k * F + cg));
#pragma unroll
        for (int i = 0; i < 8; i++) {
            float a = sA[(rg + i) * F + k];   // broadcast across warp
            acc[i][0] = fmaf(a, wv.x, acc[i][0]);
            acc[i][1] = fmaf(a, wv.y, acc[i][1]);
            acc[i][2] = fmaf(a, wv.z, acc[i][2]);
            acc[i][3] = fmaf(a, wv.w, acc[i][3]);
        }
    }

    float4 b = __ldg(reinterpret_cast<const float4*>(bias + cg));
#pragma unroll
    for (int i = 0; i < 8; i++) {
        int row = rb + rg + i;
        if (row < n_nodes) {
            float nrm = rsqrtf(fmaxf((float)g_deg[row], 1.0f));
            float4 o;
            o.x = acc[i][0] * nrm + b.x;
            o.y = acc[i][1] * nrm + b.y;
            o.z = acc[i][2] * nrm + b.z;
            o.w = acc[i][3] * nrm + b.w;
            *reinterpret_cast<float4*>(out + (long)row * F + cg) = o;
        }
    }
}

// ---------------------------------------------------------------------------
extern "C" void kernel_launch(void* const* d_in, const int* in_sizes, int n_in,
                              void* d_out, int out_size) {
    const float* feat   = (const float*)d_in[0];
    const int*   src    = (const int*)d_in[1];
    const int*   dst    = (const int*)d_in[2];
    const float* weight = (const float*)d_in[3];
    const float* bias   = (const float*)d_in[4];
    float* out = (float*)d_out;

    int n_nodes = in_sizes[0] / F;
    int n_edges = in_sizes[1];

    int scan_blocks = (n_nodes + SCAN_CHUNK - 1) / SCAN_CHUNK;
    int eb = (n_edges + 255) / 256;

    // zero deg + cursor via graph-capturable memset nodes
    void* deg_ptr = nullptr;
    void* cur_ptr = nullptr;
    cudaGetSymbolAddress(&deg_ptr, g_deg);
    cudaGetSymbolAddress(&cur_ptr, g_cursor);
    cudaMemsetAsync(deg_ptr, 0, (size_t)n_nodes * sizeof(int));
    cudaMemsetAsync(cur_ptr, 0, (size_t)n_nodes * sizeof(int));

    convert_kernel<<<1024, 256>>>(feat, (long)n_nodes * F);
    hist_kernel<<<eb, 256>>>(dst, n_edges);
    scan1_kernel<<<scan_blocks, SCAN_CHUNK>>>(n_nodes);
    scan2_kernel<<<1, SCAN_GMAX>>>(scan_blocks, n_nodes);
    scan3_kernel<<<scan_blocks, SCAN_CHUNK>>>(n_nodes);
    fill_kernel<<<eb, 256>>>(src, dst, n_edges);

    int fused_blocks = (n_nodes + GM - 1) / GM;
    fused_gather_gemm_kernel<<<fused_blocks, 256>>>(weight, bias, out, n_nodes);
}

// round 7
// speedup vs baseline: 1.1339x; 1.1339x over previous
#include <cuda_runtime.h>
#include <cuda_fp16.h>
#include <cuda_bf16.h>

#define N_NODES_MAX 100000
#define E_MAX       1600000
#define F           128
#define SCAN_CHUNK  1024
#define SCAN_GMAX   128      // ceil(100000/1024) = 98 <= 128

// Scratch (allocation-free contract: __device__ globals)
__device__ __half g_feat_h[(long)N_NODES_MAX * F]; // 25.6 MB fp16 features
__device__ float g_agg[(long)N_NODES_MAX * F];     // 51.2 MB fp32 aggregate
__device__ int   g_deg[N_NODES_MAX];
__device__ int   g_row_start[N_NODES_MAX + 1];
__device__ int   g_cursor[N_NODES_MAX];
__device__ int   g_csr_src[E_MAX];                 // 6.4 MB
__device__ int   g_block_sums[SCAN_GMAX];
__device__ int   g_block_offsets[SCAN_GMAX];

// ---------------------------------------------------------------------------
// 0. convert feat fp32 -> fp16
// ---------------------------------------------------------------------------
__global__ void convert_kernel(const float* __restrict__ feat, long total) {
    long i = (long)blockIdx.x * blockDim.x + threadIdx.x;   // float4 index
    long n4 = total / 4;
    for (; i < n4; i += (long)gridDim.x * blockDim.x) {
        float4 v = reinterpret_cast<const float4*>(feat)[i];
        __half2 h0 = __floats2half2_rn(v.x, v.y);
        __half2 h1 = __floats2half2_rn(v.z, v.w);
        uint2 packed;
        packed.x = *reinterpret_cast<unsigned*>(&h0);
        packed.y = *reinterpret_cast<unsigned*>(&h1);
        reinterpret_cast<uint2*>(g_feat_h)[i] = packed;
    }
}

// ---------------------------------------------------------------------------
// 1. histogram of dst
// ---------------------------------------------------------------------------
__global__ void hist_kernel(const int* __restrict__ dst, int n_edges) {
    int e = blockIdx.x * blockDim.x + threadIdx.x;
    if (e < n_edges) atomicAdd(&g_deg[dst[e]], 1);
}

// ---------------------------------------------------------------------------
// 2a. per-chunk sums
// ---------------------------------------------------------------------------
__global__ void __launch_bounds__(SCAN_CHUNK) scan1_kernel(int n_nodes) {
    __shared__ int s[SCAN_CHUNK];
    int t = threadIdx.x;
    int idx = blockIdx.x * SCAN_CHUNK + t;
    s[t] = (idx < n_nodes) ? g_deg[idx] : 0;
    __syncthreads();
    for (int off = SCAN_CHUNK / 2; off > 0; off >>= 1) {
        if (t < off) s[t] += s[t + off];
        __syncthreads();
    }
    if (t == 0) g_block_sums[blockIdx.x] = s[0];
}

// 2b. scan of chunk sums (single block)
__global__ void __launch_bounds__(SCAN_GMAX) scan2_kernel(int n_blocks, int n_nodes) {
    __shared__ int s[SCAN_GMAX];
    int t = threadIdx.x;
    int v = (t < n_blocks) ? g_block_sums[t] : 0;
    s[t] = v;
    __syncthreads();
    for (int off = 1; off < SCAN_GMAX; off <<= 1) {
        int add = (t >= off) ? s[t - off] : 0;
        __syncthreads();
        s[t] += add;
        __syncthreads();
    }
    if (t < n_blocks) g_block_offsets[t] = s[t] - v;   // exclusive
    if (t == SCAN_GMAX - 1) g_row_start[n_nodes] = s[SCAN_GMAX - 1];
}

// 2c. per-chunk exclusive scan + block offset -> row_start
__global__ void __launch_bounds__(SCAN_CHUNK) scan3_kernel(int n_nodes) {
    __shared__ int s[SCAN_CHUNK];
    int t = threadIdx.x;
    int idx = blockIdx.x * SCAN_CHUNK + t;
    int own = (idx < n_nodes) ? g_deg[idx] : 0;
    s[t] = own;
    __syncthreads();
    for (int off = 1; off < SCAN_CHUNK; off <<= 1) {
        int add = (t >= off) ? s[t - off] : 0;
        __syncthreads();
        s[t] += add;
        __syncthreads();
    }
    if (idx < n_nodes)
        g_row_start[idx] = g_block_offsets[blockIdx.x] + s[t] - own;
}

// ---------------------------------------------------------------------------
// 3. fill CSR: slot = row_start[dst] + cursor[dst]++
// ---------------------------------------------------------------------------
__global__ void fill_kernel(const int* __restrict__ src,
                            const int* __restrict__ dst, int n_edges) {
    int e = blockIdx.x * blockDim.x + threadIdx.x;
    if (e >= n_edges) return;
    int d = dst[e];
    int pos = atomicAdd(&g_cursor[d], 1);
    g_csr_src[g_row_start[d] + pos] = src[e];
}

// ---------------------------------------------------------------------------
// 4. gather (fp16 reads, fp32 accumulate): one warp per node, lane owns 4
// features (uint2 = 4 halves). Edge src indices shfl-broadcast, unroll 8.
// ---------------------------------------------------------------------------
__global__ void __launch_bounds__(256) gather_kernel(int n_nodes) {
    int node = blockIdx.x * (blockDim.x >> 5) + (threadIdx.x >> 5);
    if (node >= n_nodes) return;
    int lane = threadIdx.x & 31;

    int beg = g_row_start[node];
    int end = g_row_start[node + 1];

    const uint2* fh = reinterpret_cast<const uint2*>(g_feat_h);  // 32 uint2/row

    float4 acc = make_float4(0.f, 0.f, 0.f, 0.f);
    for (int i = beg; i < end; i += 32) {
        int s_reg = (i + lane < end) ? g_csr_src[i + lane] : 0;
        int cnt = min(32, end - i);
#pragma unroll 8
        for (int j = 0; j < cnt; j++) {
            int s = __shfl_sync(0xffffffffu, s_reg, j);
            uint2 raw = __ldg(fh + (long)s * 32 + lane);
            __half2 h0 = *reinterpret_cast<__half2*>(&raw.x);
            __half2 h1 = *reinterpret_cast<__half2*>(&raw.y);
            float2 f0 = __half22float2(h0);
            float2 f1 = __half22float2(h1);
            acc.x += f0.x; acc.y += f0.y;
            acc.z += f1.x; acc.w += f1.y;
        }
    }
    *reinterpret_cast<float4*>(g_agg + (long)node * F + lane * 4) = acc;
}

// ---------------------------------------------------------------------------
// 5. register-tiled GEMM + norm + bias (unchanged from best kernel).
// ---------------------------------------------------------------------------
#define GM 64
__global__ void __launch_bounds__(256) gemm_norm_kernel(
        const float* __restrict__ W,
        const float* __restrict__ bias,
        float* __restrict__ out,
        int n_nodes) {
    __shared__ float sA[GM * F];   // 32 KB

    int t = threadIdx.x;
    int rb = blockIdx.x * GM;

    {
        const float4* ap = reinterpret_cast<const float4*>(g_agg);
        float4* sp = reinterpret_cast<float4*>(sA);
#pragma unroll
        for (int i = 0; i < (GM * F / 4) / 256; i++) {
            int idx = t + i * 256;
            int row = rb + (idx >> 5);
            sp[idx] = (row < n_nodes) ? ap[(long)rb * 32 + idx]
                                      : make_float4(0.f, 0.f, 0.f, 0.f);
        }
    }
    __syncthreads();

    int cg = (t & 31) * 4;
    int rg = (t >> 5) * 8;

    float acc[8][4];
#pragma unroll
    for (int i = 0; i < 8; i++)
#pragma unroll
        for (int j = 0; j < 4; j++) acc[i][j] = 0.f;

#pragma unroll 8
    for (int k = 0; k < F; k++) {
        float4 w = __ldg(reinterpret_cast<const float4*>(W + k * F + cg));
#pragma unroll
        for (int i = 0; i < 8; i++) {
            float a = sA[(rg + i) * F + k];
            acc[i][0] = fmaf(a, w.x, acc[i][0]);
            acc[i][1] = fmaf(a, w.y, acc[i][1]);
            acc[i][2] = fmaf(a, w.z, acc[i][2]);
            acc[i][3] = fmaf(a, w.w, acc[i][3]);
        }
    }

    float4 b = __ldg(reinterpret_cast<const float4*>(bias + cg));
#pragma unroll
    for (int i = 0; i < 8; i++) {
        int row = rb + rg + i;
        if (row < n_nodes) {
            float nrm = rsqrtf(fmaxf((float)g_deg[row], 1.0f));
            float4 o;
            o.x = acc[i][0] * nrm + b.x;
            o.y = acc[i][1] * nrm + b.y;
            o.z = acc[i][2] * nrm + b.z;
            o.w = acc[i][3] * nrm + b.w;
            *reinterpret_cast<float4*>(out + (long)row * F + cg) = o;
        }
    }
}

// ---------------------------------------------------------------------------
extern "C" void kernel_launch(void* const* d_in, const int* in_sizes, int n_in,
                              void* d_out, int out_size) {
    const float* feat   = (const float*)d_in[0];
    const int*   src    = (const int*)d_in[1];
    const int*   dst    = (const int*)d_in[2];
    const float* weight = (const float*)d_in[3];
    const float* bias   = (const float*)d_in[4];
    float* out = (float*)d_out;

    int n_nodes = in_sizes[0] / F;
    int n_edges = in_sizes[1];

    int scan_blocks = (n_nodes + SCAN_CHUNK - 1) / SCAN_CHUNK;
    int eb = (n_edges + 255) / 256;

    void* deg_ptr = nullptr;
    void* cur_ptr = nullptr;
    cudaGetSymbolAddress(&deg_ptr, g_deg);
    cudaGetSymbolAddress(&cur_ptr, g_cursor);
    cudaMemsetAsync(deg_ptr, 0, (size_t)n_nodes * sizeof(int));
    cudaMemsetAsync(cur_ptr, 0, (size_t)n_nodes * sizeof(int));

    convert_kernel<<<1024, 256>>>(feat, (long)n_nodes * F);
    hist_kernel<<<eb, 256>>>(dst, n_edges);
    scan1_kernel<<<scan_blocks, SCAN_CHUNK>>>(n_nodes);
    scan2_kernel<<<1, SCAN_GMAX>>>(scan_blocks, n_nodes);
    scan3_kernel<<<scan_blocks, SCAN_CHUNK>>>(n_nodes);
    fill_kernel<<<eb, 256>>>(src, dst, n_edges);

    int warps_per_block = 256 / 32;
    int gather_blocks = (n_nodes + warps_per_block - 1) / warps_per_block;
    gather_kernel<<<gather_blocks, 256>>>(n_nodes);

    int gemm_blocks = (n_nodes + GM - 1) / GM;
    gemm_norm_kernel<<<gemm_blocks, 256>>>(weight, bias, out, n_nodes);
}

// round 9
// speedup vs baseline: 1.3574x; 1.1972x over previous
#include <cuda_runtime.h>
#include <cuda_fp16.h>
#include <cuda_bf16.h>
#include <cstdint>

#define N_NODES_MAX 100000
#define E_MAX       1600000
#define F           128
#define SCAN_CHUNK  1024
#define SCAN_GMAX   128

// ===========================================================================
// Scratch (allocation-free contract: __device__ globals)
// ===========================================================================
__device__ __half g_feat_h[(long)N_NODES_MAX * F]; // 25.6 MB fp16 features
__device__ float  g_agg[(long)N_NODES_MAX * F];    // 51.2 MB fp32 aggregate
__device__ __half g_Wh[F * F];                     // W^T fp16, n-major [n][k]
__device__ int    g_deg[N_NODES_MAX];
__device__ int    g_row_start[N_NODES_MAX + 1];
__device__ int    g_cursor[N_NODES_MAX];
__device__ int    g_csr_src[E_MAX];
__device__ int    g_block_sums[SCAN_GMAX];
__device__ int    g_block_offsets[SCAN_GMAX];

// m16n8k16 fp16 x fp16 -> fp32 (base PTX, sm_80+, no 'a' features)
#define MMA16816(d0,d1,d2,d3, a0,a1,a2,a3, b0,b1, c0,c1,c2,c3)                 \
    asm volatile(                                                              \
        "mma.sync.aligned.m16n8k16.row.col.f32.f16.f16.f32 "                   \
        "{%0,%1,%2,%3}, {%4,%5,%6,%7}, {%8,%9}, {%10,%11,%12,%13};"            \
        : "=f"(d0), "=f"(d1), "=f"(d2), "=f"(d3)                               \
        : "r"(a0), "r"(a1), "r"(a2), "r"(a3), "r"(b0), "r"(b1),                \
          "f"(c0), "f"(c1), "f"(c2), "f"(c3))

// ---------------------------------------------------------------------------
// 0a. convert feat fp32 -> fp16
// ---------------------------------------------------------------------------
__global__ void convert_kernel(const float* __restrict__ feat, long total) {
    long i = (long)blockIdx.x * blockDim.x + threadIdx.x;
    long n4 = total / 4;
    for (; i < n4; i += (long)gridDim.x * blockDim.x) {
        float4 v = reinterpret_cast<const float4*>(feat)[i];
        __half2 h0 = __floats2half2_rn(v.x, v.y);
        __half2 h1 = __floats2half2_rn(v.z, v.w);
        uint2 packed;
        packed.x = *reinterpret_cast<unsigned*>(&h0);
        packed.y = *reinterpret_cast<unsigned*>(&h1);
        reinterpret_cast<uint2*>(g_feat_h)[i] = packed;
    }
}

// ---------------------------------------------------------------------------
// 0b. W^T fp16, n-major: g_Wh[n*F + k] = W[k*F + n]
// ---------------------------------------------------------------------------
__global__ void prep_w_kernel(const float* __restrict__ W) {
    int idx = blockIdx.x * blockDim.x + threadIdx.x;
    if (idx >= F * F) return;
    int n = idx >> 7;
    int k = idx & 127;
    g_Wh[n * F + k] = __float2half_rn(W[k * F + n]);
}

// ---------------------------------------------------------------------------
// 1. histogram of dst
// ---------------------------------------------------------------------------
__global__ void hist_kernel(const int* __restrict__ dst, int n_edges) {
    int e = blockIdx.x * blockDim.x + threadIdx.x;
    if (e < n_edges) atomicAdd(&g_deg[dst[e]], 1);
}

// ---------------------------------------------------------------------------
// 2a/2b/2c: exclusive scan of degrees -> row_start
// ---------------------------------------------------------------------------
__global__ void __launch_bounds__(SCAN_CHUNK) scan1_kernel(int n_nodes) {
    __shared__ int s[SCAN_CHUNK];
    int t = threadIdx.x;
    int idx = blockIdx.x * SCAN_CHUNK + t;
    s[t] = (idx < n_nodes) ? g_deg[idx] : 0;
    __syncthreads();
    for (int off = SCAN_CHUNK / 2; off > 0; off >>= 1) {
        if (t < off) s[t] += s[t + off];
        __syncthreads();
    }
    if (t == 0) g_block_sums[blockIdx.x] = s[0];
}

__global__ void __launch_bounds__(SCAN_GMAX) scan2_kernel(int n_blocks, int n_nodes) {
    __shared__ int s[SCAN_GMAX];
    int t = threadIdx.x;
    int v = (t < n_blocks) ? g_block_sums[t] : 0;
    s[t] = v;
    __syncthreads();
    for (int off = 1; off < SCAN_GMAX; off <<= 1) {
        int add = (t >= off) ? s[t - off] : 0;
        __syncthreads();
        s[t] += add;
        __syncthreads();
    }
    if (t < n_blocks) g_block_offsets[t] = s[t] - v;
    if (t == SCAN_GMAX - 1) g_row_start[n_nodes] = s[SCAN_GMAX - 1];
}

__global__ void __launch_bounds__(SCAN_CHUNK) scan3_kernel(int n_nodes) {
    __shared__ int s[SCAN_CHUNK];
    int t = threadIdx.x;
    int idx = blockIdx.x * SCAN_CHUNK + t;
    int own = (idx < n_nodes) ? g_deg[idx] : 0;
    s[t] = own;
    __syncthreads();
    for (int off = 1; off < SCAN_CHUNK; off <<= 1) {
        int add = (t >= off) ? s[t - off] : 0;
        __syncthreads();
        s[t] += add;
        __syncthreads();
    }
    if (idx < n_nodes)
        g_row_start[idx] = g_block_offsets[blockIdx.x] + s[t] - own;
}

// ---------------------------------------------------------------------------
// 3. fill CSR
// ---------------------------------------------------------------------------
__global__ void fill_kernel(const int* __restrict__ src,
                            const int* __restrict__ dst, int n_edges) {
    int e = blockIdx.x * blockDim.x + threadIdx.x;
    if (e >= n_edges) return;
    int d = dst[e];
    int pos = atomicAdd(&g_cursor[d], 1);
    g_csr_src[g_row_start[d] + pos] = src[e];
}

// ---------------------------------------------------------------------------
// 4. gather (fp16 reads, fp32 accumulate): one warp per node (unchanged)
// ---------------------------------------------------------------------------
__global__ void __launch_bounds__(256) gather_kernel(int n_nodes) {
    int node = blockIdx.x * (blockDim.x >> 5) + (threadIdx.x >> 5);
    if (node >= n_nodes) return;
    int lane = threadIdx.x & 31;

    int beg = g_row_start[node];
    int end = g_row_start[node + 1];

    const uint2* fh = reinterpret_cast<const uint2*>(g_feat_h);

    float4 acc = make_float4(0.f, 0.f, 0.f, 0.f);
    for (int i = beg; i < end; i += 32) {
        int s_reg = (i + lane < end) ? g_csr_src[i + lane] : 0;
        int cnt = min(32, end - i);
#pragma unroll 8
        for (int j = 0; j < cnt; j++) {
            int s = __shfl_sync(0xffffffffu, s_reg, j);
            uint2 raw = __ldg(fh + (long)s * 32 + lane);
            __half2 h0 = *reinterpret_cast<__half2*>(&raw.x);
            __half2 h1 = *reinterpret_cast<__half2*>(&raw.y);
            float2 f0 = __half22float2(h0);
            float2 f1 = __half22float2(h1);
            acc.x += f0.x; acc.y += f0.y;
            acc.z += f1.x; acc.w += f1.y;
        }
    }
    *reinterpret_cast<float4*>(g_agg + (long)node * F + lane * 4) = acc;
}

// ---------------------------------------------------------------------------
// 5. HMMA GEMM + norm + bias.
// Block: 256 threads / 8 warps, 128 rows. sA = fp16 agg tile (row pad 136
// halves -> conflict-free quad LDS). Warp w owns rows [w*16, w*16+16),
// all 128 cols. All 8 k-tile A fragments hoisted to registers; B fragments
// read straight from L1-resident g_Wh (32 KB, n-major).
// ---------------------------------------------------------------------------
#define PADH 136
__global__ void __launch_bounds__(256) mma_gemm_kernel(
        const float* __restrict__ bias,
        float* __restrict__ out, int n_nodes) {
    __shared__ __half sA[128 * PADH];   // ~34.8 KB

    int t = threadIdx.x;
    int warp = t >> 5;
    int lane = t & 31;
    int g   = lane >> 2;       // groupID 0..7
    int tig = lane & 3;        // thread-in-group 0..3
    int rb = blockIdx.x * 128;

    // ---- stage agg tile as fp16 (coalesced float2 -> half2) ----
    {
        for (int i = 0; i < 32; i++) {
            int idx = t + i * 256;          // half2 index, 64 per row
            int row = idx >> 6;
            int c2 = idx & 63;
            __half2 h;
            if (rb + row < n_nodes) {
                float2 v = *reinterpret_cast<const float2*>(
                    g_agg + (long)(rb + row) * F + c2 * 2);
                h = __floats2half2_rn(v.x, v.y);
            } else {
                h = __floats2half2_rn(0.f, 0.f);
            }
            *reinterpret_cast<__half2*>(&sA[row * PADH + c2 * 2]) = h;
        }
    }
    __syncthreads();

    int mrow = warp * 16;

    // ---- hoist all A fragments: 8 k-tiles x 4 regs ----
    uint32_t a[8][4];
#pragma unroll
    for (int kt = 0; kt < 8; kt++) {
        int k0 = kt * 16 + tig * 2;
        a[kt][0] = *reinterpret_cast<const uint32_t*>(&sA[(mrow + g)     * PADH + k0]);
        a[kt][1] = *reinterpret_cast<const uint32_t*>(&sA[(mrow + g + 8) * PADH + k0]);
        a[kt][2] = *reinterpret_cast<const uint32_t*>(&sA[(mrow + g)     * PADH + k0 + 8]);
        a[kt][3] = *reinterpret_cast<const uint32_t*>(&sA[(mrow + g + 8) * PADH + k0 + 8]);
    }

    int row0 = rb + mrow + g;
    int row1 = row0 + 8;
    float nrm0 = (row0 < n_nodes) ? rsqrtf(fmaxf((float)g_deg[row0], 1.0f)) : 0.f;
    float nrm1 = (row1 < n_nodes) ? rsqrtf(fmaxf((float)g_deg[row1], 1.0f)) : 0.f;

    const uint32_t* Wh32 = reinterpret_cast<const uint32_t*>(g_Wh);  // 64 u32/row

#pragma unroll
    for (int nt = 0; nt < 16; nt++) {
        int nb = nt * 8;
        int ncol = nb + g;                 // this thread's B column
        float c0 = 0.f, c1 = 0.f, c2 = 0.f, c3 = 0.f;
#pragma unroll
        for (int kt = 0; kt < 8; kt++) {
            // b0 = {W^T[n][k0], W^T[n][k0+1]}, b1 = {+8,+9} : contiguous half2
            uint32_t b0 = __ldg(Wh32 + ncol * 64 + kt * 8 + tig);
            uint32_t b1 = __ldg(Wh32 + ncol * 64 + kt * 8 + tig + 4);
            MMA16816(c0, c1, c2, c3,
                     a[kt][0], a[kt][1], a[kt][2], a[kt][3],
                     b0, b1, c0, c1, c2, c3);
        }
        float2 bv = __ldg(reinterpret_cast<const float2*>(bias + nb + tig * 2));
        if (row0 < n_nodes) {
            float2 o0;
            o0.x = c0 * nrm0 + bv.x;
            o0.y = c1 * nrm0 + bv.y;
            *reinterpret_cast<float2*>(out + (long)row0 * F + nb + tig * 2) = o0;
        }
        if (row1 < n_nodes) {
            float2 o1;
            o1.x = c2 * nrm1 + bv.x;
            o1.y = c3 * nrm1 + bv.y;
            *reinterpret_cast<float2*>(out + (long)row1 * F + nb + tig * 2) = o1;
        }
    }
}

// ---------------------------------------------------------------------------
extern "C" void kernel_launch(void* const* d_in, const int* in_sizes, int n_in,
                              void* d_out, int out_size) {
    const float* feat   = (const float*)d_in[0];
    const int*   src    = (const int*)d_in[1];
    const int*   dst    = (const int*)d_in[2];
    const float* weight = (const float*)d_in[3];
    const float* bias   = (const float*)d_in[4];
    float* out = (float*)d_out;

    int n_nodes = in_sizes[0] / F;
    int n_edges = in_sizes[1];

    int scan_blocks = (n_nodes + SCAN_CHUNK - 1) / SCAN_CHUNK;
    int eb = (n_edges + 255) / 256;

    void* deg_ptr = nullptr;
    void* cur_ptr = nullptr;
    cudaGetSymbolAddress(&deg_ptr, g_deg);
    cudaGetSymbolAddress(&cur_ptr, g_cursor);
    cudaMemsetAsync(deg_ptr, 0, (size_t)n_nodes * sizeof(int));
    cudaMemsetAsync(cur_ptr, 0, (size_t)n_nodes * sizeof(int));

    convert_kernel<<<1024, 256>>>(feat, (long)n_nodes * F);
    prep_w_kernel<<<(F * F + 255) / 256, 256>>>(weight);
    hist_kernel<<<eb, 256>>>(dst, n_edges);
    scan1_kernel<<<scan_blocks, SCAN_CHUNK>>>(n_nodes);
    scan2_kernel<<<1, SCAN_GMAX>>>(scan_blocks, n_nodes);
    scan3_kernel<<<scan_blocks, SCAN_CHUNK>>>(n_nodes);
    fill_kernel<<<eb, 256>>>(src, dst, n_edges);

    int warps_per_block = 256 / 32;
    int gather_blocks = (n_nodes + warps_per_block - 1) / warps_per_block;
    gather_kernel<<<gather_blocks, 256>>>(n_nodes);

    int gemm_blocks = (n_nodes + 127) / 128;
    mma_gemm_kernel<<<gemm_blocks, 256>>>(bias, out, n_nodes);
}

// round 12
// speedup vs baseline: 1.3770x; 1.0144x over previous
#include <cuda_runtime.h>
#include <cuda_fp16.h>
#include <cuda_bf16.h>
#include <cstdint>

#define N_NODES_MAX 100000
#define E_MAX       1600000
#define F           128
#define SC          4096          // elements per scan block (1024 thr x 4)
#define SCAN_BMAX   32

// ===========================================================================
// Scratch (allocation-free contract: __device__ globals)
// ===========================================================================
__device__ __half g_feat_h[(long)N_NODES_MAX * F]; // 25.6 MB fp16 features
__device__ float  g_agg[(long)N_NODES_MAX * F];    // 51.2 MB fp32 aggregate
__device__ uint4  g_Wpack[2048];                   // packed B frags, 32 KB
__device__ int    g_deg[N_NODES_MAX];
__device__ int    g_row_start[N_NODES_MAX + 1];
__device__ int    g_cursor[N_NODES_MAX];
__device__ int    g_csr_src[E_MAX];
__device__ int    g_chain[SCAN_BMAX];              // chained-scan release slots

// m16n8k16 fp16 x fp16 -> fp32 (base PTX, sm_80+, no 'a' features)
#define MMA16816(d0,d1,d2,d3, a0,a1,a2,a3, b0,b1, c0,c1,c2,c3)                 \
    asm volatile(                                                              \
        "mma.sync.aligned.m16n8k16.row.col.f32.f16.f16.f32 "                   \
        "{%0,%1,%2,%3}, {%4,%5,%6,%7}, {%8,%9}, {%10,%11,%12,%13};"            \
        : "=f"(d0), "=f"(d1), "=f"(d2), "=f"(d3)                               \
        : "r"(a0), "r"(a1), "r"(a2), "r"(a3), "r"(b0), "r"(b1),                \
          "f"(c0), "f"(c1), "f"(c2), "f"(c3))

// ---------------------------------------------------------------------------
// 0a. convert feat fp32 -> fp16
// ---------------------------------------------------------------------------
__global__ void convert_kernel(const float* __restrict__ feat, long total) {
    long i = (long)blockIdx.x * blockDim.x + threadIdx.x;
    long n4 = total / 4;
    for (; i < n4; i += (long)gridDim.x * blockDim.x) {
        float4 v = reinterpret_cast<const float4*>(feat)[i];
        __half2 h0 = __floats2half2_rn(v.x, v.y);
        __half2 h1 = __floats2half2_rn(v.z, v.w);
        uint2 packed;
        packed.x = *reinterpret_cast<unsigned*>(&h0);
        packed.y = *reinterpret_cast<unsigned*>(&h1);
        reinterpret_cast<uint2*>(g_feat_h)[i] = packed;
    }
}

// ---------------------------------------------------------------------------
// 0b. pack B fragments in MMA consumption order.
// Entry (nt, ktp, tig, g): uint4 { b0(kt0), b1(kt0), b0(kt1), b1(kt1) }
// where b0(kt) = half2{ W[k][ncol], W[k+1][ncol] }, k = kt*16 + tig*2
//       b1(kt) = same at k+8; ncol = nt*8 + g; kt0 = 2*ktp, kt1 = kt0+1.
// Warp access (g fastest over 4-lane groups, tig over lanes) spans one
// contiguous 512B region -> 4 wavefronts per LDG.128.
// ---------------------------------------------------------------------------
__global__ void prep_w_kernel(const float* __restrict__ W) {
    int idx = blockIdx.x * blockDim.x + threadIdx.x;  // 0..2047
    if (idx >= 2048) return;
    int g   = idx & 7;
    int tig = (idx >> 3) & 3;
    int ktp = (idx >> 5) & 3;
    int nt  = idx >> 7;
    int ncol = nt * 8 + g;

    auto pack = [&](int k) -> uint32_t {
        __half2 h = __floats2half2_rn(W[k * F + ncol], W[(k + 1) * F + ncol]);
        return *reinterpret_cast<uint32_t*>(&h);
    };
    int k0 = (2 * ktp) * 16 + tig * 2;
    int k1 = (2 * ktp + 1) * 16 + tig * 2;
    uint4 bb;
    bb.x = pack(k0);
    bb.y = pack(k0 + 8);
    bb.z = pack(k1);
    bb.w = pack(k1 + 8);
    g_Wpack[((nt * 4 + ktp) * 4 + tig) * 8 + g] = bb;
}

// ---------------------------------------------------------------------------
// 1. histogram of dst
// ---------------------------------------------------------------------------
__global__ void hist_kernel(const int* __restrict__ dst, int n_edges) {
    int e = blockIdx.x * blockDim.x + threadIdx.x;
    if (e < n_edges) atomicAdd(&g_deg[dst[e]], 1);
}

// ---------------------------------------------------------------------------
// 2. single-pass chained exclusive scan: g_deg -> g_row_start.
// 25 blocks (<= 148 SMs, all resident -> forward progress guaranteed).
// g_chain[] preset to -1; block b publishes its inclusive prefix total.
// ---------------------------------------------------------------------------
__global__ void __launch_bounds__(1024) scan_chain_kernel(int n_nodes, int n_blocks) {
    __shared__ int ssum[1024];
    __shared__ int s_prev;
    int b = blockIdx.x, t = threadIdx.x;
    int base = b * SC + t * 4;

    int4 v = make_int4(0, 0, 0, 0);
    if (base + 3 < n_nodes) {
        v = *reinterpret_cast<const int4*>(g_deg + base);
    } else {
        if (base + 0 < n_nodes) v.x = g_deg[base + 0];
        if (base + 1 < n_nodes) v.y = g_deg[base + 1];
        if (base + 2 < n_nodes) v.z = g_deg[base + 2];
        if (base + 3 < n_nodes) v.w = g_deg[base + 3];
    }
    int tsum = v.x + v.y + v.z + v.w;

    ssum[t] = tsum;
    __syncthreads();
    for (int off = 1; off < 1024; off <<= 1) {
        int add = (t >= off) ? ssum[t - off] : 0;
        __syncthreads();
        ssum[t] += add;
        __syncthreads();
    }
    int incl = ssum[t];               // inclusive over thread sums
    int excl_thread = incl - tsum;

    if (t == 0) {
        int prev = 0;
        if (b > 0) {
            while ((prev = atomicAdd(&g_chain[b - 1], 0)) < 0) { }
        }
        s_prev = prev;
        __threadfence();
        atomicExch(&g_chain[b], prev + ssum[1023]);
    }
    __syncthreads();

    int e0 = s_prev + excl_thread;
    if (base + 0 < n_nodes) g_row_start[base + 0] = e0;
    if (base + 1 < n_nodes) g_row_start[base + 1] = e0 + v.x;
    if (base + 2 < n_nodes) g_row_start[base + 2] = e0 + v.x + v.y;
    if (base + 3 < n_nodes) g_row_start[base + 3] = e0 + v.x + v.y + v.z;
    if (b == n_blocks - 1 && t == 1023) g_row_start[n_nodes] = s_prev + incl;
}

// ---------------------------------------------------------------------------
// 3. fill CSR
// ---------------------------------------------------------------------------
__global__ void fill_kernel(const int* __restrict__ src,
                            const int* __restrict__ dst, int n_edges) {
    int e = blockIdx.x * blockDim.x + threadIdx.x;
    if (e >= n_edges) return;
    int d = dst[e];
    int pos = atomicAdd(&g_cursor[d], 1);
    g_csr_src[g_row_start[d] + pos] = src[e];
}

// ---------------------------------------------------------------------------
// 4. gather (fp16 reads, fp32 accumulate): one warp per node (unchanged)
// ---------------------------------------------------------------------------
__global__ void __launch_bounds__(256) gather_kernel(int n_nodes) {
    int node = blockIdx.x * (blockDim.x >> 5) + (threadIdx.x >> 5);
    if (node >= n_nodes) return;
    int lane = threadIdx.x & 31;

    int beg = g_row_start[node];
    int end = g_row_start[node + 1];

    const uint2* fh = reinterpret_cast<const uint2*>(g_feat_h);

    float4 acc = make_float4(0.f, 0.f, 0.f, 0.f);
    for (int i = beg; i < end; i += 32) {
        int s_reg = (i + lane < end) ? g_csr_src[i + lane] : 0;
        int cnt = min(32, end - i);
#pragma unroll 8
        for (int j = 0; j < cnt; j++) {
            int s = __shfl_sync(0xffffffffu, s_reg, j);
            uint2 raw = __ldg(fh + (long)s * 32 + lane);
            __half2 h0 = *reinterpret_cast<__half2*>(&raw.x);
            __half2 h1 = *reinterpret_cast<__half2*>(&raw.y);
            float2 f0 = __half22float2(h0);
            float2 f1 = __half22float2(h1);
            acc.x += f0.x; acc.y += f0.y;
            acc.z += f1.x; acc.w += f1.y;
        }
    }
    *reinterpret_cast<float4*>(g_agg + (long)node * F + lane * 4) = acc;
}

// ---------------------------------------------------------------------------
// 5. HMMA GEMM + norm + bias. B fragments from packed layout: one LDG.128
// per (nt, ktp), fully coalesced 512B per warp.
// ---------------------------------------------------------------------------
#define PADH 136
__global__ void __launch_bounds__(256) mma_gemm_kernel(
        const float* __restrict__ bias,
        float* __restrict__ out, int n_nodes) {
    __shared__ __half sA[128 * PADH];   // ~34.8 KB

    int t = threadIdx.x;
    int warp = t >> 5;
    int lane = t & 31;
    int g   = lane >> 2;       // groupID 0..7
    int tig = lane & 3;        // thread-in-group 0..3
    int rb = blockIdx.x * 128;

    // ---- stage agg tile as fp16 ----
    {
        for (int i = 0; i < 32; i++) {
            int idx = t + i * 256;          // half2 index, 64 per row
            int row = idx >> 6;
            int c2 = idx & 63;
            __half2 h;
            if (rb + row < n_nodes) {
                float2 v = *reinterpret_cast<const float2*>(
                    g_agg + (long)(rb + row) * F + c2 * 2);
                h = __floats2half2_rn(v.x, v.y);
            } else {
                h = __floats2half2_rn(0.f, 0.f);
            }
            *reinterpret_cast<__half2*>(&sA[row * PADH + c2 * 2]) = h;
        }
    }
    __syncthreads();

    int mrow = warp * 16;

    // ---- hoist all A fragments: 8 k-tiles x 4 regs ----
    uint32_t a[8][4];
#pragma unroll
    for (int kt = 0; kt < 8; kt++) {
        int k0 = kt * 16 + tig * 2;
        a[kt][0] = *reinterpret_cast<const uint32_t*>(&sA[(mrow + g)     * PADH + k0]);
        a[kt][1] = *reinterpret_cast<const uint32_t*>(&sA[(mrow + g + 8) * PADH + k0]);
        a[kt][2] = *reinterpret_cast<const uint32_t*>(&sA[(mrow + g)     * PADH + k0 + 8]);
        a[kt][3] = *reinterpret_cast<const uint32_t*>(&sA[(mrow + g + 8) * PADH + k0 + 8]);
    }

    int row0 = rb + mrow + g;
    int row1 = row0 + 8;
    float nrm0 = (row0 < n_nodes) ? rsqrtf(fmaxf((float)g_deg[row0], 1.0f)) : 0.f;
    float nrm1 = (row1 < n_nodes) ? rsqrtf(fmaxf((float)g_deg[row1], 1.0f)) : 0.f;

#pragma unroll
    for (int nt = 0; nt < 16; nt++) {
        int nb = nt * 8;
        float c0 = 0.f, c1 = 0.f, c2 = 0.f, c3 = 0.f;
#pragma unroll
        for (int ktp = 0; ktp < 4; ktp++) {
            uint4 bb = __ldg(&g_Wpack[((nt * 4 + ktp) * 4 + tig) * 8 + g]);
            int kt0 = 2 * ktp, kt1 = kt0 + 1;
            MMA16816(c0, c1, c2, c3,
                     a[kt0][0], a[kt0][1], a[kt0][2], a[kt0][3],
                     bb.x, bb.y, c0, c1, c2, c3);
            MMA16816(c0, c1, c2, c3,
                     a[kt1][0], a[kt1][1], a[kt1][2], a[kt1][3],
                     bb.z, bb.w, c0, c1, c2, c3);
        }
        float2 bv = __ldg(reinterpret_cast<const float2*>(bias + nb + tig * 2));
        if (row0 < n_nodes) {
            float2 o0;
            o0.x = c0 * nrm0 + bv.x;
            o0.y = c1 * nrm0 + bv.y;
            *reinterpret_cast<float2*>(out + (long)row0 * F + nb + tig * 2) = o0;
        }
        if (row1 < n_nodes) {
            float2 o1;
            o1.x = c2 * nrm1 + bv.x;
            o1.y = c3 * nrm1 + bv.y;
            *reinterpret_cast<float2*>(out + (long)row1 * F + nb + tig * 2) = o1;
        }
    }
}

// ---------------------------------------------------------------------------
extern "C" void kernel_launch(void* const* d_in, const int* in_sizes, int n_in,
                              void* d_out, int out_size) {
    const float* feat   = (const float*)d_in[0];
    const int*   src    = (const int*)d_in[1];
    const int*   dst    = (const int*)d_in[2];
    const float* weight = (const float*)d_in[3];
    const float* bias   = (const float*)d_in[4];
    float* out = (float*)d_out;

    int n_nodes = in_sizes[0] / F;
    int n_edges = in_sizes[1];

    int eb = (n_edges + 255) / 256;
    int scan_blocks = (n_nodes + SC - 1) / SC;

    void* deg_ptr = nullptr;
    void* cur_ptr = nullptr;
    void* chain_ptr = nullptr;
    cudaGetSymbolAddress(&deg_ptr, g_deg);
    cudaGetSymbolAddress(&cur_ptr, g_cursor);
    cudaGetSymbolAddress(&chain_ptr, g_chain);
    cudaMemsetAsync(deg_ptr, 0, (size_t)n_nodes * sizeof(int));
    cudaMemsetAsync(cur_ptr, 0, (size_t)n_nodes * sizeof(int));
    cudaMemsetAsync(chain_ptr, 0xFF, SCAN_BMAX * sizeof(int));   // -1 sentinels

    convert_kernel<<<1024, 256>>>(feat, (long)n_nodes * F);
    prep_w_kernel<<<8, 256>>>(weight);
    hist_kernel<<<eb, 256>>>(dst, n_edges);
    scan_chain_kernel<<<scan_blocks, 1024>>>(n_nodes, scan_blocks);
    fill_kernel<<<eb, 256>>>(src, dst, n_edges);

    int warps_per_block = 256 / 32;
    int gather_blocks = (n_nodes + warps_per_block - 1) / warps_per_block;
    gather_kernel<<<gather_blocks, 256>>>(n_nodes);

    int gemm_blocks = (n_nodes + 127) / 128;
    mma_gemm_kernel<<<gemm_blocks, 256>>>(bias, out, n_nodes);
}

// round 13
// speedup vs baseline: 1.4752x; 1.0713x over previous
#include <cuda_runtime.h>
#include <cuda_fp16.h>
#include <cuda_bf16.h>
#include <cstdint>

#define N_NODES_MAX 100000
#define E_MAX       1600000
#define F           128
#define SC          4096          // elements per scan block (1024 thr x 4)
#define SCAN_BMAX   32

// ===========================================================================
// Scratch (allocation-free contract: __device__ globals)
// ===========================================================================
__device__ __half g_feat_h[(long)N_NODES_MAX * F]; // 25.6 MB fp16 features
__device__ float  g_agg[(long)N_NODES_MAX * F];    // 51.2 MB fp32 aggregate
__device__ uint4  g_Wpack[2048];                   // packed B frags, 32 KB
__device__ int    g_deg[N_NODES_MAX];
__device__ int    g_row_start[N_NODES_MAX + 1];
__device__ int    g_cursor[N_NODES_MAX];
__device__ int    g_csr_src[E_MAX];
__device__ int    g_aggr[SCAN_BMAX];               // per-block scan aggregates

// m16n8k16 fp16 x fp16 -> fp32 (base PTX, sm_80+, no 'a' features)
#define MMA16816(d0,d1,d2,d3, a0,a1,a2,a3, b0,b1, c0,c1,c2,c3)                 \
    asm volatile(                                                              \
        "mma.sync.aligned.m16n8k16.row.col.f32.f16.f16.f32 "                   \
        "{%0,%1,%2,%3}, {%4,%5,%6,%7}, {%8,%9}, {%10,%11,%12,%13};"            \
        : "=f"(d0), "=f"(d1), "=f"(d2), "=f"(d3)                               \
        : "r"(a0), "r"(a1), "r"(a2), "r"(a3), "r"(b0), "r"(b1),                \
          "f"(c0), "f"(c1), "f"(c2), "f"(c3))

// ---------------------------------------------------------------------------
// 0a. convert feat fp32 -> fp16
// ---------------------------------------------------------------------------
__global__ void convert_kernel(const float* __restrict__ feat, long total) {
    long i = (long)blockIdx.x * blockDim.x + threadIdx.x;
    long n4 = total / 4;
    for (; i < n4; i += (long)gridDim.x * blockDim.x) {
        float4 v = reinterpret_cast<const float4*>(feat)[i];
        __half2 h0 = __floats2half2_rn(v.x, v.y);
        __half2 h1 = __floats2half2_rn(v.z, v.w);
        uint2 packed;
        packed.x = *reinterpret_cast<unsigned*>(&h0);
        packed.y = *reinterpret_cast<unsigned*>(&h1);
        reinterpret_cast<uint2*>(g_feat_h)[i] = packed;
    }
}

// ---------------------------------------------------------------------------
// 0b. pack B fragments in MMA consumption order (validated R10/R12 layout).
// ---------------------------------------------------------------------------
__global__ void prep_w_kernel(const float* __restrict__ W) {
    int idx = blockIdx.x * blockDim.x + threadIdx.x;  // 0..2047
    if (idx >= 2048) return;
    int g   = idx & 7;
    int tig = (idx >> 3) & 3;
    int ktp = (idx >> 5) & 3;
    int nt  = idx >> 7;
    int ncol = nt * 8 + g;

    auto pack = [&](int k) -> uint32_t {
        __half2 h = __floats2half2_rn(W[k * F + ncol], W[(k + 1) * F + ncol]);
        return *reinterpret_cast<uint32_t*>(&h);
    };
    int k0 = (2 * ktp) * 16 + tig * 2;
    int k1 = (2 * ktp + 1) * 16 + tig * 2;
    uint4 bb;
    bb.x = pack(k0);
    bb.y = pack(k0 + 8);
    bb.z = pack(k1);
    bb.w = pack(k1 + 8);
    g_Wpack[((nt * 4 + ktp) * 4 + tig) * 8 + g] = bb;
}

// ---------------------------------------------------------------------------
// 1. histogram of dst
// ---------------------------------------------------------------------------
__global__ void hist_kernel(const int* __restrict__ dst, int n_edges) {
    int e = blockIdx.x * blockDim.x + threadIdx.x;
    if (e < n_edges) atomicAdd(&g_deg[dst[e]], 1);
}

// ---------------------------------------------------------------------------
// 2. single-pass decoupled-aggregate exclusive scan: g_deg -> g_row_start.
// Warp-shuffle scans (3 barriers). Each block publishes its aggregate
// IMMEDIATELY (no chain); t0 then sums predecessor aggregates (all blocks
// resident: 25 <= 148 SMs, forward progress guaranteed).
// ---------------------------------------------------------------------------
__global__ void __launch_bounds__(1024) scan_chain_kernel(int n_nodes, int n_blocks) {
    __shared__ int swarp[32];
    __shared__ int s_total;
    __shared__ int s_prev;
    int b = blockIdx.x, t = threadIdx.x;
    int lane = t & 31, wid = t >> 5;
    int base = b * SC + t * 4;

    int4 v = make_int4(0, 0, 0, 0);
    if (base + 3 < n_nodes) {
        v = *reinterpret_cast<const int4*>(g_deg + base);
    } else {
        if (base + 0 < n_nodes) v.x = g_deg[base + 0];
        if (base + 1 < n_nodes) v.y = g_deg[base + 1];
        if (base + 2 < n_nodes) v.z = g_deg[base + 2];
        if (base + 3 < n_nodes) v.w = g_deg[base + 3];
    }
    int tsum = v.x + v.y + v.z + v.w;

    // warp inclusive scan of thread sums
    int incl = tsum;
#pragma unroll
    for (int off = 1; off < 32; off <<= 1) {
        int ngh = __shfl_up_sync(0xffffffffu, incl, off);
        if (lane >= off) incl += ngh;
    }
    if (lane == 31) swarp[wid] = incl;
    __syncthreads();

    // warp 0 scans the 32 warp totals
    if (wid == 0) {
        int wv = swarp[lane];
        int wincl = wv;
#pragma unroll
        for (int off = 1; off < 32; off <<= 1) {
            int ngh = __shfl_up_sync(0xffffffffu, wincl, off);
            if (lane >= off) wincl += ngh;
        }
        swarp[lane] = wincl - wv;           // exclusive warp offset
        if (lane == 31) s_total = wincl;    // block aggregate
    }
    __syncthreads();

    // publish aggregate immediately; then sum predecessors
    if (t == 0) {
        atomicExch(&g_aggr[b], s_total);
        int prev = 0;
        for (int j = 0; j < b; j++) {
            int a;
            while ((a = atomicAdd(&g_aggr[j], 0)) < 0) { }
            prev += a;
        }
        s_prev = prev;
    }
    __syncthreads();

    int e0 = s_prev + swarp[wid] + incl - tsum;
    if (base + 0 < n_nodes) g_row_start[base + 0] = e0;
    if (base + 1 < n_nodes) g_row_start[base + 1] = e0 + v.x;
    if (base + 2 < n_nodes) g_row_start[base + 2] = e0 + v.x + v.y;
    if (base + 3 < n_nodes) g_row_start[base + 3] = e0 + v.x + v.y + v.z;
    if (b == n_blocks - 1 && t == 1023) g_row_start[n_nodes] = s_prev + s_total;
}

// ---------------------------------------------------------------------------
// 3. fill CSR
// ---------------------------------------------------------------------------
__global__ void fill_kernel(const int* __restrict__ src,
                            const int* __restrict__ dst, int n_edges) {
    int e = blockIdx.x * blockDim.x + threadIdx.x;
    if (e >= n_edges) return;
    int d = dst[e];
    int pos = atomicAdd(&g_cursor[d], 1);
    g_csr_src[g_row_start[d] + pos] = src[e];
}

// ---------------------------------------------------------------------------
// 4. gather (fp16 reads, fp32 accumulate): one warp per node (unchanged)
// ---------------------------------------------------------------------------
__global__ void __launch_bounds__(256) gather_kernel(int n_nodes) {
    int node = blockIdx.x * (blockDim.x >> 5) + (threadIdx.x >> 5);
    if (node >= n_nodes) return;
    int lane = threadIdx.x & 31;

    int beg = g_row_start[node];
    int end = g_row_start[node + 1];

    const uint2* fh = reinterpret_cast<const uint2*>(g_feat_h);

    float4 acc = make_float4(0.f, 0.f, 0.f, 0.f);
    for (int i = beg; i < end; i += 32) {
        int s_reg = (i + lane < end) ? g_csr_src[i + lane] : 0;
        int cnt = min(32, end - i);
#pragma unroll 8
        for (int j = 0; j < cnt; j++) {
            int s = __shfl_sync(0xffffffffu, s_reg, j);
            uint2 raw = __ldg(fh + (long)s * 32 + lane);
            __half2 h0 = *reinterpret_cast<__half2*>(&raw.x);
            __half2 h1 = *reinterpret_cast<__half2*>(&raw.y);
            float2 f0 = __half22float2(h0);
            float2 f1 = __half22float2(h1);
            acc.x += f0.x; acc.y += f0.y;
            acc.z += f1.x; acc.w += f1.y;
        }
    }
    *reinterpret_cast<float4*>(g_agg + (long)node * F + lane * 4) = acc;
}

// ---------------------------------------------------------------------------
// 5. HMMA GEMM + norm + bias (unchanged from R12).
// ---------------------------------------------------------------------------
#define PADH 136
__global__ void __launch_bounds__(256) mma_gemm_kernel(
        const float* __restrict__ bias,
        float* __restrict__ out, int n_nodes) {
    __shared__ __half sA[128 * PADH];   // ~34.8 KB

    int t = threadIdx.x;
    int warp = t >> 5;
    int lane = t & 31;
    int g   = lane >> 2;       // groupID 0..7
    int tig = lane & 3;        // thread-in-group 0..3
    int rb = blockIdx.x * 128;

    // ---- stage agg tile as fp16 ----
    {
        for (int i = 0; i < 32; i++) {
            int idx = t + i * 256;          // half2 index, 64 per row
            int row = idx >> 6;
            int c2 = idx & 63;
            __half2 h;
            if (rb + row < n_nodes) {
                float2 v = *reinterpret_cast<const float2*>(
                    g_agg + (long)(rb + row) * F + c2 * 2);
                h = __floats2half2_rn(v.x, v.y);
            } else {
                h = __floats2half2_rn(0.f, 0.f);
            }
            *reinterpret_cast<__half2*>(&sA[row * PADH + c2 * 2]) = h;
        }
    }
    __syncthreads();

    int mrow = warp * 16;

    // ---- hoist all A fragments: 8 k-tiles x 4 regs ----
    uint32_t a[8][4];
#pragma unroll
    for (int kt = 0; kt < 8; kt++) {
        int k0 = kt * 16 + tig * 2;
        a[kt][0] = *reinterpret_cast<const uint32_t*>(&sA[(mrow + g)     * PADH + k0]);
        a[kt][1] = *reinterpret_cast<const uint32_t*>(&sA[(mrow + g + 8) * PADH + k0]);
        a[kt][2] = *reinterpret_cast<const uint32_t*>(&sA[(mrow + g)     * PADH + k0 + 8]);
        a[kt][3] = *reinterpret_cast<const uint32_t*>(&sA[(mrow + g + 8) * PADH + k0 + 8]);
    }

    int row0 = rb + mrow + g;
    int row1 = row0 + 8;
    float nrm0 = (row0 < n_nodes) ? rsqrtf(fmaxf((float)g_deg[row0], 1.0f)) : 0.f;
    float nrm1 = (row1 < n_nodes) ? rsqrtf(fmaxf((float)g_deg[row1], 1.0f)) : 0.f;

#pragma unroll
    for (int nt = 0; nt < 16; nt++) {
        int nb = nt * 8;
        float c0 = 0.f, c1 = 0.f, c2 = 0.f, c3 = 0.f;
#pragma unroll
        for (int ktp = 0; ktp < 4; ktp++) {
            uint4 bb = __ldg(&g_Wpack[((nt * 4 + ktp) * 4 + tig) * 8 + g]);
            int kt0 = 2 * ktp, kt1 = kt0 + 1;
            MMA16816(c0, c1, c2, c3,
                     a[kt0][0], a[kt0][1], a[kt0][2], a[kt0][3],
                     bb.x, bb.y, c0, c1, c2, c3);
            MMA16816(c0, c1, c2, c3,
                     a[kt1][0], a[kt1][1], a[kt1][2], a[kt1][3],
                     bb.z, bb.w, c0, c1, c2, c3);
        }
        float2 bv = __ldg(reinterpret_cast<const float2*>(bias + nb + tig * 2));
        if (row0 < n_nodes) {
            float2 o0;
            o0.x = c0 * nrm0 + bv.x;
            o0.y = c1 * nrm0 + bv.y;
            *reinterpret_cast<float2*>(out + (long)row0 * F + nb + tig * 2) = o0;
        }
        if (row1 < n_nodes) {
            float2 o1;
            o1.x = c2 * nrm1 + bv.x;
            o1.y = c3 * nrm1 + bv.y;
            *reinterpret_cast<float2*>(out + (long)row1 * F + nb + tig * 2) = o1;
        }
    }
}

// ---------------------------------------------------------------------------
extern "C" void kernel_launch(void* const* d_in, const int* in_sizes, int n_in,
                              void* d_out, int out_size) {
    const float* feat   = (const float*)d_in[0];
    const int*   src    = (const int*)d_in[1];
    const int*   dst    = (const int*)d_in[2];
    const float* weight = (const float*)d_in[3];
    const float* bias   = (const float*)d_in[4];
    float* out = (float*)d_out;

    int n_nodes = in_sizes[0] / F;
    int n_edges = in_sizes[1];

    int eb = (n_edges + 255) / 256;
    int scan_blocks = (n_nodes + SC - 1) / SC;

    void* deg_ptr = nullptr;
    void* cur_ptr = nullptr;
    void* aggr_ptr = nullptr;
    cudaGetSymbolAddress(&deg_ptr, g_deg);
    cudaGetSymbolAddress(&cur_ptr, g_cursor);
    cudaGetSymbolAddress(&aggr_ptr, g_aggr);
    cudaMemsetAsync(deg_ptr, 0, (size_t)n_nodes * sizeof(int));
    cudaMemsetAsync(cur_ptr, 0, (size_t)n_nodes * sizeof(int));
    cudaMemsetAsync(aggr_ptr, 0xFF, SCAN_BMAX * sizeof(int));   // -1 sentinels

    convert_kernel<<<1024, 256>>>(feat, (long)n_nodes * F);
    prep_w_kernel<<<8, 256>>>(weight);
    hist_kernel<<<eb, 256>>>(dst, n_edges);
    scan_chain_kernel<<<scan_blocks, 1024>>>(n_nodes, scan_blocks);
    fill_kernel<<<eb, 256>>>(src, dst, n_edges);

    int warps_per_block = 256 / 32;
    int gather_blocks = (n_nodes + warps_per_block - 1) / warps_per_block;
    gather_kernel<<<gather_blocks, 256>>>(n_nodes);

    int gemm_blocks = (n_nodes + 127) / 128;
    mma_gemm_kernel<<<gemm_blocks, 256>>>(bias, out, n_nodes);
}